// round 10
// baseline (speedup 1.0000x reference)
#include <cuda_runtime.h>
#include <cuda_bf16.h>
#include <stdint.h>

#define BATCH 16
#define CDIM 256
#define HW 4096
#define KC 32                 // k-chunk (bf16 elems per stage)
#define KSPLIT 8
#define KSEG (HW / KSPLIT)    // 512
#define NKCS (KSEG / KC)      // 16 chunks per CTA
#define SSTR 40               // smem row stride in bf16 (80B; conflict-free ldsm)
#define STAGES 4
#define TAU 8.0f

// dynamic smem layout (bytes)
#define STAGE_BYTES (128 * SSTR * 2)          // 10240 per matrix per stage
#define SA_OFF(s) ((s) * STAGE_BYTES)         // A: [0, 40960)
#define SB_OFF(s) (STAGES * STAGE_BYTES + (s) * STAGE_BYTES)   // B: [40960, 81920)
#define YN_OFF (2 * STAGES * STAGE_BYTES)     // 81920, float[128]
#define MB_OFF (YN_OFF + 512)                 // 82432, 4 x (full,empty) u64 pairs
#define SMEM_BYTES (MB_OFF + 128)

__device__ float g_part[KSPLIT][BATCH * CDIM * CDIM];   // 32 MB partial dist
__device__ int   g_idx[BATCH * CDIM];

// ---------------- helpers ----------------
__device__ __forceinline__ uint32_t bf2(float x, float y) {
    __nv_bfloat162 h = __floats2bfloat162_rn(x, y);
    return *reinterpret_cast<uint32_t*>(&h);
}
__device__ __forceinline__ uint32_t smaddr(const void* p) {
    return (uint32_t)__cvta_generic_to_shared(p);
}
__device__ __forceinline__ void ldsm4(uint32_t a, uint32_t* r) {
    asm volatile("ldmatrix.sync.aligned.m8n8.x4.shared.b16 {%0,%1,%2,%3}, [%4];"
                 : "=r"(r[0]), "=r"(r[1]), "=r"(r[2]), "=r"(r[3]) : "r"(a));
}
__device__ __forceinline__ void mma_bf16(float* d, const uint32_t* a, const uint32_t* b) {
    asm volatile("mma.sync.aligned.m16n8k16.row.col.f32.bf16.bf16.f32 "
                 "{%0,%1,%2,%3}, {%4,%5,%6,%7}, {%8,%9}, {%0,%1,%2,%3};"
                 : "+f"(d[0]), "+f"(d[1]), "+f"(d[2]), "+f"(d[3])
                 : "r"(a[0]), "r"(a[1]), "r"(a[2]), "r"(a[3]), "r"(b[0]), "r"(b[1]));
}
__device__ __forceinline__ void mbar_init(uint32_t a, uint32_t cnt) {
    asm volatile("mbarrier.init.shared.b64 [%0], %1;" :: "r"(a), "r"(cnt) : "memory");
}
__device__ __forceinline__ void mbar_arrive(uint32_t a) {
    asm volatile("mbarrier.arrive.shared.b64 _, [%0];" :: "r"(a) : "memory");
}
__device__ __forceinline__ void mbar_wait(uint32_t mbar, uint32_t parity) {
    asm volatile("{\n\t.reg .pred P;\n"
                 "WL_%=:\n\tmbarrier.try_wait.parity.acquire.cta.shared::cta.b64 P, [%0], %1, 0x989680;\n\t"
                 "@P bra WD_%=;\n\tbra WL_%=;\nWD_%=:\n\t}"
                 :: "r"(mbar), "r"(parity) : "memory");
}

// ---------------------------------------------------------------------------
// 1) partial dist^2 over one k-segment (bf16-hi MMA), warp-specialized:
//    threads 0-511  : 16 consumer warps, 4(i)x4(j), warp tile 32x32
//    threads 512-767: 8 producer warps, LDG fp32 -> cvt bf16 -> STS, 4-stage ring
// ---------------------------------------------------------------------------
__global__ void __launch_bounds__(768) gemm_ws_kernel(const float* __restrict__ X,
                                                      const float* __restrict__ Y) {
    extern __shared__ __align__(16) uint8_t sm[];
    const int t  = threadIdx.x;
    const int b  = blockIdx.z >> 3;
    const int ks = blockIdx.z & 7;
    const int i0 = blockIdx.y * 128;
    const int j0 = blockIdx.x * 128;

    const uint32_t smu = smaddr(sm);
    const uint32_t mb  = smu + MB_OFF;   // full(s)=mb+s*16, empty(s)=mb+s*16+8
    float* ynS = (float*)(sm + YN_OFF);

    if (t == 0) {
#pragma unroll
        for (int s = 0; s < STAGES; ++s) {
            mbar_init(mb + s * 16, 256);       // full: producer arrivals
            mbar_init(mb + s * 16 + 8, 512);   // empty: consumer arrivals
        }
    }
    __syncthreads();

    // consumer state (declared at fn scope so acc survives into epilogue)
    const int lane = t & 31;
    const int w    = t >> 5;             // consumer warps: 0..15
    const int i0w  = (w >> 2) * 32;
    const int j0w  = (w & 3) * 32;
    const int arow = i0w + (lane & 15);
    const int acol = (lane >> 4) * 8;
    const int bn   = j0w + (lane & 7) + ((lane >> 4) << 3);
    const int bk   = ((lane >> 3) & 1) * 8;
    float acc[2][4][4];
#pragma unroll
    for (int m = 0; m < 2; ++m)
#pragma unroll
        for (int n = 0; n < 4; ++n)
#pragma unroll
            for (int e = 0; e < 4; ++e) acc[m][n][e] = 0.f;

    if (t >= 512) {
        // ---------------- producer ----------------
        const int tp = t - 512;
        const int o  = tp & 7;           // float4-lane within 128B line
        const int rb = tp >> 3;          // 0..31
        const float* rowptr[8];
#pragma unroll
        for (int pp = 0; pp < 8; ++pp) {
            const int tr = rb + 32 * pp;   // 0..255: A rows 0-127, B rows 128-255
            rowptr[pp] = (pp < 4 ? X + (size_t)(b * CDIM + i0 + tr) * HW
                                 : Y + (size_t)(b * CDIM + j0 + tr - 128) * HW)
                         + ks * KSEG + o * 4;
        }
        float ysq[4] = {0.f, 0.f, 0.f, 0.f};

        int s = 0, ph = 1;               // phase 1: first STAGES empty-waits pass
        for (int kc = 0; kc < NKCS; ++kc) {
            mbar_wait(mb + s * 16 + 8, ph);
#pragma unroll
            for (int pp = 0; pp < 8; ++pp) {
                float4 v = *(const float4*)(rowptr[pp] + kc * KC);
                if (pp >= 4)
                    ysq[pp - 4] += v.x * v.x + v.y * v.y + v.z * v.z + v.w * v.w;
                const int tr = rb + 32 * pp;
                __nv_bfloat16* dst =
                    (pp < 4) ? (__nv_bfloat16*)(sm + SA_OFF(s)) + tr * SSTR + o * 4
                             : (__nv_bfloat16*)(sm + SB_OFF(s)) + (tr - 128) * SSTR + o * 4;
                *(uint2*)dst = make_uint2(bf2(v.x, v.y), bf2(v.z, v.w));
            }
            mbar_arrive(mb + s * 16);    // full
            if (++s == STAGES) { s = 0; ph ^= 1; }
        }
        // partial ynorm (exact fp32): reduce over the 8 lanes sharing a row
#pragma unroll
        for (int q = 0; q < 4; ++q) {
            float sv = ysq[q];
            sv += __shfl_xor_sync(0xffffffffu, sv, 1);
            sv += __shfl_xor_sync(0xffffffffu, sv, 2);
            sv += __shfl_xor_sync(0xffffffffu, sv, 4);
            if (o == 0) ynS[rb + 32 * q] = sv;
        }
    } else {
        // ---------------- consumer ----------------
        int s = 0, ph = 0;
        for (int kc = 0; kc < NKCS; ++kc) {
            mbar_wait(mb + s * 16, ph);  // full
            const uint32_t sab = smu + SA_OFF(s);
            const uint32_t sbb = smu + SB_OFF(s);
#pragma unroll
            for (int st = 0; st < 2; ++st) {   // two k16 steps per stage
                uint32_t ah0[4], ah1[4], bh0[4], bh1[4];
                const uint32_t ao = 2u * (arow * SSTR + st * 16 + acol);
                ldsm4(sab + ao, ah0);
                ldsm4(sab + ao + 2u * 16 * SSTR, ah1);
                const uint32_t bo = 2u * (bn * SSTR + st * 16 + bk);
                ldsm4(sbb + bo, bh0);
                ldsm4(sbb + bo + 2u * 16 * SSTR, bh1);
                mma_bf16(acc[0][0], ah0, bh0);
                mma_bf16(acc[0][1], ah0, bh0 + 2);
                mma_bf16(acc[0][2], ah0, bh1);
                mma_bf16(acc[0][3], ah0, bh1 + 2);
                mma_bf16(acc[1][0], ah1, bh0);
                mma_bf16(acc[1][1], ah1, bh0 + 2);
                mma_bf16(acc[1][2], ah1, bh1);
                mma_bf16(acc[1][3], ah1, bh1 + 2);
            }
            mbar_arrive(mb + s * 16 + 8);  // empty
            if (++s == STAGES) { s = 0; ph ^= 1; }
        }
    }

    __syncthreads();   // ynS written by producers; MMA done

    if (t < 512) {
        float* gout = g_part[ks];
#pragma unroll
        for (int mi = 0; mi < 2; ++mi) {
#pragma unroll
            for (int nb = 0; nb < 4; ++nb) {
                const int jc = j0w + nb * 8 + (lane & 3) * 2;
                float2 yn = *(float2*)&ynS[jc];
                const int grow = b * CDIM + i0 + i0w + mi * 16 + (lane >> 2);
                float2 d0, d1;
                d0.x = yn.x - 2.f * acc[mi][nb][0];
                d0.y = yn.y - 2.f * acc[mi][nb][1];
                d1.x = yn.x - 2.f * acc[mi][nb][2];
                d1.y = yn.y - 2.f * acc[mi][nb][3];
                *(float2*)&gout[(size_t)grow * CDIM + j0 + jc] = d0;
                *(float2*)&gout[(size_t)(grow + 8) * CDIM + j0 + jc] = d1;
            }
        }
    }
}

// ---------------------------------------------------------------------------
// 2) argmin (sum of 8 partials) with exact-fp32 rescue. One block per row.
// ---------------------------------------------------------------------------
__global__ void __launch_bounds__(256) rescore_kernel(const float* __restrict__ X,
                                                      const float* __restrict__ Y) {
    const int row = blockIdx.x;           // b*CDIM + i
    const int b   = row >> 8;
    const int t   = threadIdx.x;

    __shared__ float s_red[8];
    __shared__ float s_minv;
    __shared__ int   s_cnt;
    __shared__ int   s_lst[256];

    const size_t off = (size_t)row * CDIM + t;
    float d = 0.f;
#pragma unroll
    for (int k = 0; k < KSPLIT; ++k) d += g_part[k][off];

    float vv = d;
#pragma unroll
    for (int o = 16; o; o >>= 1) vv = fminf(vv, __shfl_down_sync(0xffffffffu, vv, o));
    if ((t & 31) == 0) s_red[t >> 5] = vv;
    __syncthreads();
    if (t == 0) {
        float m = s_red[0];
#pragma unroll
        for (int i = 1; i < 8; ++i) m = fminf(m, s_red[i]);
        s_minv = m;
        s_cnt = 0;
    }
    __syncthreads();

    if (d <= s_minv + TAU) {
        int pos = atomicAdd(&s_cnt, 1);
        s_lst[pos] = t;
    }
    __syncthreads();

    const int n = s_cnt;
    if (n == 1) {
        if (t == 0) g_idx[row] = s_lst[0];
        return;
    }

    const float* xr = X + (size_t)row * HW;
    float bestv = 3.4e38f;
    int   bestj = 0x7fffffff;
    for (int c = 0; c < n; ++c) {
        const int j = s_lst[c];
        const float* yr = Y + (size_t)(b * CDIM + j) * HW;
        float s = 0.f;
#pragma unroll
        for (int q = 0; q < 4; ++q) {
            float4 xv = ((const float4*)xr)[t + q * 256];
            float4 yv = ((const float4*)yr)[t + q * 256];
            float dx = xv.x - yv.x, dy = xv.y - yv.y, dz = xv.z - yv.z, dw = xv.w - yv.w;
            s += dx * dx + dy * dy + dz * dz + dw * dw;
        }
#pragma unroll
        for (int o = 16; o; o >>= 1) s += __shfl_down_sync(0xffffffffu, s, o);
        if ((t & 31) == 0) s_red[t >> 5] = s;
        __syncthreads();
        if (t == 0) {
            float tot = 0.f;
#pragma unroll
            for (int i = 0; i < 8; ++i) tot += s_red[i];
            if (tot < bestv || (tot == bestv && j < bestj)) { bestv = tot; bestj = j; }
        }
        __syncthreads();
    }
    if (t == 0) g_idx[row] = bestj;
}

// ---------------------------------------------------------------------------
// 3) gather: out[b,i,:] = Y[b, g_idx[b,i], :]
// ---------------------------------------------------------------------------
__global__ void __launch_bounds__(256) gather_kernel(const float* __restrict__ Y,
                                                     float* __restrict__ out) {
    int row  = blockIdx.x >> 2;
    int part = blockIdx.x & 3;
    int bb   = row >> 8;
    int src  = g_idx[row];
    const float4* yp = (const float4*)(Y + (size_t)(bb * CDIM + src) * HW);
    float4*       op = (float4*)(out + (size_t)row * HW);
    int e = part * 256 + threadIdx.x;
    op[e] = yp[e];
}

// ---------------------------------------------------------------------------
extern "C" void kernel_launch(void* const* d_in, const int* in_sizes, int n_in,
                              void* d_out, int out_size) {
    const float* x = (const float*)d_in[0];
    const float* y = (const float*)d_in[1];
    float* out = (float*)d_out;

    cudaFuncSetAttribute(gemm_ws_kernel,
                         cudaFuncAttributeMaxDynamicSharedMemorySize, SMEM_BYTES);

    dim3 g(CDIM / 128, CDIM / 128, BATCH * KSPLIT);   // 2 x 2 x 128 = 512 CTAs
    gemm_ws_kernel<<<g, 768, SMEM_BYTES>>>(x, y);

    rescore_kernel<<<BATCH * CDIM, 256>>>(x, y);

    gather_kernel<<<BATCH * CDIM * 4, 256>>>(y, out);
}

// round 11
// speedup vs baseline: 1.5535x; 1.5535x over previous
#include <cuda_runtime.h>
#include <stdint.h>

#define BATCH 16
#define CDIM 256
#define HW 4096
#define KC 16                  // k per chunk (fp32 elems)
#define KSPLIT 8
#define KSEG (HW / KSPLIT)     // 512
#define NKCS (KSEG / KC)       // 32 chunks
#define STAGES 4
#define SSTRF 20               // smem row stride in floats (80B; conflict-free)
#define TAU 8.0f

#define STG_BYTES (128 * 80)              // per matrix per stage (10240)
#define STAGE_STRIDE (2 * STG_BYTES)
#define SA_OFF(s) ((s) * STAGE_STRIDE)
#define SB_OFF(s) ((s) * STAGE_STRIDE + STG_BYTES)
#define SMEM_BYTES (STAGES * STAGE_STRIDE)   // 81920

__device__ float g_part[KSPLIT][BATCH * CDIM * CDIM];   // dot partials
__device__ float g_ynp[KSPLIT][BATCH * CDIM];           // |y|^2 partials
__device__ int   g_idx[BATCH * CDIM];

// ---------------- helpers ----------------
__device__ __forceinline__ uint32_t smaddr(const void* p) {
    return (uint32_t)__cvta_generic_to_shared(p);
}
__device__ __forceinline__ void cpasync16(uint32_t dst, const float* src) {
    asm volatile("cp.async.cg.shared.global [%0], [%1], 16;" :: "r"(dst), "l"(src));
}
__device__ __forceinline__ void cp_commit() {
    asm volatile("cp.async.commit_group;" ::: "memory");
}
__device__ __forceinline__ void cp_wait2() {
    asm volatile("cp.async.wait_group 2;" ::: "memory");
}
__device__ __forceinline__ void mma_tf32(float* d, const uint32_t* a, const uint32_t* b) {
    asm volatile("mma.sync.aligned.m16n8k8.row.col.f32.tf32.tf32.f32 "
                 "{%0,%1,%2,%3}, {%4,%5,%6,%7}, {%8,%9}, {%0,%1,%2,%3};"
                 : "+f"(d[0]), "+f"(d[1]), "+f"(d[2]), "+f"(d[3])
                 : "r"(a[0]), "r"(a[1]), "r"(a[2]), "r"(a[3]), "r"(b[0]), "r"(b[1]));
}

// ---------------------------------------------------------------------------
// 1) dot-product partials over one k-segment, tf32 MMA straight from fp32 smem.
//    CTA 128(i) x 128(j), 512 threads, 16 warps 4(i)x4(j), warp tile 32x32.
//    4-stage cp.async ring, prefetch distance 3. blockIdx.y==0 CTAs also
//    accumulate |y|^2 partials from the B smem tiles.
// ---------------------------------------------------------------------------
__global__ void __launch_bounds__(512, 2) gemm_tf32_kernel(const float* __restrict__ X,
                                                           const float* __restrict__ Y) {
    extern __shared__ __align__(16) uint8_t sm[];
    const uint32_t smu = smaddr(sm);

    const int t  = threadIdx.x;
    const int b  = blockIdx.z >> 3;
    const int ks = blockIdx.z & 7;
    const int i0 = blockIdx.y * 128;
    const int j0 = blockIdx.x * 128;

    // loader mapping: tr = tile row (0..127), o = 16B segment (0..3)
    const int o  = t & 3;
    const int tr = t >> 2;
    const float* aSrc = X + (size_t)(b * CDIM + i0 + tr) * HW + ks * KSEG + o * 4;
    const float* bSrc = Y + (size_t)(b * CDIM + j0 + tr) * HW + ks * KSEG + o * 4;
    const uint32_t rowDst = smu + (uint32_t)tr * 80u + (uint32_t)o * 16u;

    // consumer mapping
    const int lane = t & 31;
    const int w    = t >> 5;
    const int i0w  = (w >> 2) * 32;
    const int j0w  = (w & 3) * 32;
    const int gr   = lane >> 2;
    const int gc   = lane & 3;

    // ynorm mapping (by==0 CTAs only)
    const bool doYn = (blockIdx.y == 0);
    const int yj = t >> 2, yq = t & 3;
    float ysq = 0.f;

    float acc[2][4][4];
#pragma unroll
    for (int m = 0; m < 2; ++m)
#pragma unroll
        for (int n = 0; n < 4; ++n)
#pragma unroll
            for (int e = 0; e < 4; ++e) acc[m][n][e] = 0.f;

    // prologue: prefetch chunks 0..2
#pragma unroll
    for (int pc = 0; pc < 3; ++pc) {
        const int s = pc & 3;
        cpasync16(rowDst + SA_OFF(s), aSrc + pc * KC);
        cpasync16(rowDst + SB_OFF(s), bSrc + pc * KC);
        cp_commit();
    }

    for (int kc = 0; kc < NKCS; ++kc) {
        cp_wait2();          // group kc complete (2 younger groups may be pending)
        __syncthreads();     // all threads' data visible; stage kc-1 fully consumed

        const int s = kc & 3;
        const uint32_t* sa32 = (const uint32_t*)(sm + SA_OFF(s));
        const uint32_t* sb32 = (const uint32_t*)(sm + SB_OFF(s));

#pragma unroll
        for (int st = 0; st < 2; ++st) {     // two k8 steps per chunk
            const int k0 = st * 8;
            uint32_t af[2][4];
#pragma unroll
            for (int mi = 0; mi < 2; ++mi) {
                const int row = i0w + mi * 16 + gr;
                af[mi][0] = sa32[row * SSTRF + k0 + gc];
                af[mi][1] = sa32[(row + 8) * SSTRF + k0 + gc];
                af[mi][2] = sa32[row * SSTRF + k0 + gc + 4];
                af[mi][3] = sa32[(row + 8) * SSTRF + k0 + gc + 4];
            }
            uint32_t bf[4][2];
#pragma unroll
            for (int nb = 0; nb < 4; ++nb) {
                const int n = j0w + nb * 8 + gr;
                bf[nb][0] = sb32[n * SSTRF + k0 + gc];
                bf[nb][1] = sb32[n * SSTRF + k0 + gc + 4];
            }
#pragma unroll
            for (int mi = 0; mi < 2; ++mi)
#pragma unroll
                for (int nb = 0; nb < 4; ++nb)
                    mma_tf32(acc[mi][nb], af[mi], bf[nb]);
        }

        if (doYn) {          // |y|^2 partial from the fp32 B tile in smem
            const float4 v = *(const float4*)((const float*)(sm + SB_OFF(s))
                                              + yj * SSTRF + yq * 4);
            ysq += v.x * v.x + v.y * v.y + v.z * v.z + v.w * v.w;
        }

        // prefetch chunk kc+3 into stage (kc-1)&3 (safe: consumed, barrier above)
        if (kc + 3 < NKCS) {
            const int sn = (kc + 3) & 3;
            cpasync16(rowDst + SA_OFF(sn), aSrc + (kc + 3) * KC);
            cpasync16(rowDst + SB_OFF(sn), bSrc + (kc + 3) * KC);
        }
        cp_commit();         // commit every iter (possibly empty) -> uniform wait
    }

    if (doYn) {
        ysq += __shfl_xor_sync(0xffffffffu, ysq, 1);
        ysq += __shfl_xor_sync(0xffffffffu, ysq, 2);
        if (yq == 0) g_ynp[ks][b * CDIM + j0 + yj] = ysq;
    }

    // epilogue: store raw dot partials
    float* gout = g_part[ks];
#pragma unroll
    for (int mi = 0; mi < 2; ++mi) {
#pragma unroll
        for (int nb = 0; nb < 4; ++nb) {
            const int jc = j0w + nb * 8 + gc * 2;
            const int grow = b * CDIM + i0 + i0w + mi * 16 + gr;
            *(float2*)&gout[(size_t)grow * CDIM + j0 + jc] =
                make_float2(acc[mi][nb][0], acc[mi][nb][1]);
            *(float2*)&gout[(size_t)(grow + 8) * CDIM + j0 + jc] =
                make_float2(acc[mi][nb][2], acc[mi][nb][3]);
        }
    }
}

// ---------------------------------------------------------------------------
// 2) argmin of (yn[j] - 2*dot) with exact-fp32 rescue. One block per row.
// ---------------------------------------------------------------------------
__global__ void __launch_bounds__(256) rescore_kernel(const float* __restrict__ X,
                                                      const float* __restrict__ Y) {
    const int row = blockIdx.x;           // b*CDIM + i
    const int b   = row >> 8;
    const int t   = threadIdx.x;

    __shared__ float s_red[8];
    __shared__ float s_minv;
    __shared__ int   s_cnt;
    __shared__ int   s_lst[256];

    const size_t off = (size_t)row * CDIM + t;
    float dot = 0.f, yn = 0.f;
#pragma unroll
    for (int k = 0; k < KSPLIT; ++k) {
        dot += g_part[k][off];
        yn  += g_ynp[k][b * CDIM + t];
    }
    float d = yn - 2.f * dot;

    float vv = d;
#pragma unroll
    for (int o = 16; o; o >>= 1) vv = fminf(vv, __shfl_down_sync(0xffffffffu, vv, o));
    if ((t & 31) == 0) s_red[t >> 5] = vv;
    __syncthreads();
    if (t == 0) {
        float m = s_red[0];
#pragma unroll
        for (int i = 1; i < 8; ++i) m = fminf(m, s_red[i]);
        s_minv = m;
        s_cnt = 0;
    }
    __syncthreads();

    if (d <= s_minv + TAU) {
        int pos = atomicAdd(&s_cnt, 1);
        s_lst[pos] = t;
    }
    __syncthreads();

    const int n = s_cnt;
    if (n == 1) {
        if (t == 0) g_idx[row] = s_lst[0];
        return;
    }

    const float* xr = X + (size_t)row * HW;
    float bestv = 3.4e38f;
    int   bestj = 0x7fffffff;
    for (int c = 0; c < n; ++c) {
        const int j = s_lst[c];
        const float* yr = Y + (size_t)(b * CDIM + j) * HW;
        float s = 0.f;
#pragma unroll
        for (int q = 0; q < 4; ++q) {
            float4 xv = ((const float4*)xr)[t + q * 256];
            float4 yv = ((const float4*)yr)[t + q * 256];
            float dx = xv.x - yv.x, dy = xv.y - yv.y, dz = xv.z - yv.z, dw = xv.w - yv.w;
            s += dx * dx + dy * dy + dz * dz + dw * dw;
        }
#pragma unroll
        for (int o = 16; o; o >>= 1) s += __shfl_down_sync(0xffffffffu, s, o);
        if ((t & 31) == 0) s_red[t >> 5] = s;
        __syncthreads();
        if (t == 0) {
            float tot = 0.f;
#pragma unroll
            for (int i = 0; i < 8; ++i) tot += s_red[i];
            if (tot < bestv || (tot == bestv && j < bestj)) { bestv = tot; bestj = j; }
        }
        __syncthreads();
    }
    if (t == 0) g_idx[row] = bestj;
}

// ---------------------------------------------------------------------------
// 3) gather: out[b,i,:] = Y[b, g_idx[b,i], :]
// ---------------------------------------------------------------------------
__global__ void __launch_bounds__(256) gather_kernel(const float* __restrict__ Y,
                                                     float* __restrict__ out) {
    int row  = blockIdx.x >> 2;
    int part = blockIdx.x & 3;
    int bb   = row >> 8;
    int src  = g_idx[row];
    const float4* yp = (const float4*)(Y + (size_t)(bb * CDIM + src) * HW);
    float4*       op = (float4*)(out + (size_t)row * HW);
    int e = part * 256 + threadIdx.x;
    op[e] = yp[e];
}

// ---------------------------------------------------------------------------
extern "C" void kernel_launch(void* const* d_in, const int* in_sizes, int n_in,
                              void* d_out, int out_size) {
    const float* x = (const float*)d_in[0];
    const float* y = (const float*)d_in[1];
    float* out = (float*)d_out;

    cudaFuncSetAttribute(gemm_tf32_kernel,
                         cudaFuncAttributeMaxDynamicSharedMemorySize, SMEM_BYTES);

    dim3 g(CDIM / 128, CDIM / 128, BATCH * KSPLIT);   // 2 x 2 x 128 = 512 CTAs
    gemm_tf32_kernel<<<g, 512, SMEM_BYTES>>>(x, y);

    rescore_kernel<<<BATCH * CDIM, 256>>>(x, y);

    gather_kernel<<<BATCH * CDIM * 4, 256>>>(y, out);
}

// round 12
// speedup vs baseline: 1.9445x; 1.2517x over previous
#include <cuda_runtime.h>
#include <cuda_bf16.h>
#include <stdint.h>

#define BATCH 16
#define CDIM 256
#define HW 4096
#define KC 16                  // k per chunk (fp32 elems) = one k16 MMA step
#define KSPLIT 8
#define KSEG (HW / KSPLIT)     // 512
#define NKCS (KSEG / KC)       // 32 chunks
#define SSTR 40                // bf16 smem row stride (80B; conflict-free ldsm)
#define TAU 8.0f

// dynamic smem layout (bytes):
// fp32 ring: 3 stages x (A 8KB + B 8KB)          [0, 49152)
// bf16 A double buffer: 2 x 10240                [49152, 69632)
// bf16 B double buffer: 2 x 10240                [69632, 90112)
#define F32_STG 16384
#define F32A(s) ((s) * F32_STG)
#define F32B(s) ((s) * F32_STG + 8192)
#define BFA(p) (49152 + (p) * 10240)
#define BFB(p) (69632 + (p) * 10240)
#define SMEM_BYTES 90112

__device__ float g_part[KSPLIT][BATCH * CDIM * CDIM];   // dot partials
__device__ float g_ynp[KSPLIT][BATCH * CDIM];           // |y|^2 partials
__device__ int   g_idx[BATCH * CDIM];

// ---------------- helpers ----------------
__device__ __forceinline__ uint32_t bf2(float x, float y) {
    __nv_bfloat162 h = __floats2bfloat162_rn(x, y);
    return *reinterpret_cast<uint32_t*>(&h);
}
__device__ __forceinline__ uint32_t smaddr(const void* p) {
    return (uint32_t)__cvta_generic_to_shared(p);
}
__device__ __forceinline__ void cpasync16(uint32_t dst, const float* src) {
    asm volatile("cp.async.cg.shared.global [%0], [%1], 16;" :: "r"(dst), "l"(src));
}
__device__ __forceinline__ void cp_commit() {
    asm volatile("cp.async.commit_group;" ::: "memory");
}
__device__ __forceinline__ void cp_wait2() {
    asm volatile("cp.async.wait_group 2;" ::: "memory");
}
__device__ __forceinline__ void ldsm4(uint32_t a, uint32_t* r) {
    asm volatile("ldmatrix.sync.aligned.m8n8.x4.shared.b16 {%0,%1,%2,%3}, [%4];"
                 : "=r"(r[0]), "=r"(r[1]), "=r"(r[2]), "=r"(r[3]) : "r"(a));
}
__device__ __forceinline__ void mma_bf16(float* d, const uint32_t* a, const uint32_t* b) {
    asm volatile("mma.sync.aligned.m16n8k16.row.col.f32.bf16.bf16.f32 "
                 "{%0,%1,%2,%3}, {%4,%5,%6,%7}, {%8,%9}, {%0,%1,%2,%3};"
                 : "+f"(d[0]), "+f"(d[1]), "+f"(d[2]), "+f"(d[3])
                 : "r"(a[0]), "r"(a[1]), "r"(a[2]), "r"(a[3]), "r"(b[0]), "r"(b[1]));
}

// ---------------------------------------------------------------------------
// 1) dot partials over one k-segment. cp.async fp32 ring (3 stages) ->
//    in-smem cvt to bf16 (double buffer) -> ldsm + m16n8k16 bf16 MMA.
//    CTA 128(i) x 128(j), 512 threads, 16 warps 4(i)x4(j), warp tile 32x32.
// ---------------------------------------------------------------------------
__global__ void __launch_bounds__(512, 2) gemm_kernel(const float* __restrict__ X,
                                                      const float* __restrict__ Y) {
    extern __shared__ __align__(16) uint8_t sm[];
    const uint32_t smu = smaddr(sm);

    const int t  = threadIdx.x;
    const int b  = blockIdx.z >> 3;
    const int ks = blockIdx.z & 7;
    const int i0 = blockIdx.y * 128;
    const int j0 = blockIdx.x * 128;

    // per-thread slice: row tr (0..127), 16B segment o (0..3) of the k16 chunk
    const int o  = t & 3;
    const int tr = t >> 2;
    const float* aSrc = X + (size_t)(b * CDIM + i0 + tr) * HW + ks * KSEG + o * 4;
    const float* bSrc = Y + (size_t)(b * CDIM + j0 + tr) * HW + ks * KSEG + o * 4;
    const uint32_t f32dst = (uint32_t)tr * 64u + (uint32_t)o * 16u;   // within a stage
    const uint32_t bfoff  = 2u * ((uint32_t)tr * SSTR + (uint32_t)o * 4u);  // bytes

    // consumer fragment mapping (R7-verified, one k16 step per chunk)
    const int lane = t & 31;
    const int w    = t >> 5;
    const int i0w  = (w >> 2) * 32;
    const int j0w  = (w & 3) * 32;
    const uint32_t aoff = 2u * ((uint32_t)(i0w + (lane & 15)) * SSTR + (uint32_t)((lane >> 4) * 8));
    const uint32_t boff = 2u * ((uint32_t)(j0w + (lane & 7) + ((lane >> 4) << 3)) * SSTR
                                + (uint32_t)(((lane >> 3) & 1) * 8));

    const bool doYn = (blockIdx.y == 0);
    float ysq = 0.f;

    float acc[2][4][4];
#pragma unroll
    for (int m = 0; m < 2; ++m)
#pragma unroll
        for (int n = 0; n < 4; ++n)
#pragma unroll
            for (int e = 0; e < 4; ++e) acc[m][n][e] = 0.f;

    // prologue: prefetch chunks 0..2
#pragma unroll
    for (int pc = 0; pc < 3; ++pc) {
        cpasync16(smu + F32A(pc) + f32dst, aSrc + pc * KC);
        cpasync16(smu + F32B(pc) + f32dst, bSrc + pc * KC);
        cp_commit();
    }

    for (int kc = 0; kc < NKCS; ++kc) {
        const int s = kc % 3;
        const int p = kc & 1;

        cp_wait2();    // own cp.async for stage s complete (own-data visibility)

        // cvt: read back own 16B, convert, store to bf16 tile p
        float4 va = *(const float4*)((const float*)(sm + F32A(s) + f32dst));
        float4 vb = *(const float4*)((const float*)(sm + F32B(s) + f32dst));
        if (doYn) ysq += vb.x * vb.x + vb.y * vb.y + vb.z * vb.z + vb.w * vb.w;
        *(uint2*)(sm + BFA(p) + bfoff) = make_uint2(bf2(va.x, va.y), bf2(va.z, va.w));
        *(uint2*)(sm + BFB(p) + bfoff) = make_uint2(bf2(vb.x, vb.y), bf2(vb.z, vb.w));

        __syncthreads();   // bf16 tile p complete; fp32 stage s consumed by all;
                           // also separates ldsm(kc-1) from any future STS into p^1

        // refill stage s with chunk kc+3
        if (kc + 3 < NKCS) {
            cpasync16(smu + F32A(s) + f32dst, aSrc + (kc + 3) * KC);
            cpasync16(smu + F32B(s) + f32dst, bSrc + (kc + 3) * KC);
        }
        cp_commit();   // uniform: one group per iteration

        // consume: 4 ldsm.x4 + 8 MMA (k16)
        uint32_t ah0[4], ah1[4], bh0[4], bh1[4];
        ldsm4(smu + BFA(p) + aoff, ah0);
        ldsm4(smu + BFA(p) + aoff + 2u * 16 * SSTR, ah1);
        ldsm4(smu + BFB(p) + boff, bh0);
        ldsm4(smu + BFB(p) + boff + 2u * 16 * SSTR, bh1);
        mma_bf16(acc[0][0], ah0, bh0);
        mma_bf16(acc[0][1], ah0, bh0 + 2);
        mma_bf16(acc[0][2], ah0, bh1);
        mma_bf16(acc[0][3], ah0, bh1 + 2);
        mma_bf16(acc[1][0], ah1, bh0);
        mma_bf16(acc[1][1], ah1, bh0 + 2);
        mma_bf16(acc[1][2], ah1, bh1);
        mma_bf16(acc[1][3], ah1, bh1 + 2);
    }

    if (doYn) {        // |y|^2 partial (exact fp32): 4 lanes per row
        ysq += __shfl_xor_sync(0xffffffffu, ysq, 1);
        ysq += __shfl_xor_sync(0xffffffffu, ysq, 2);
        if (o == 0) g_ynp[ks][b * CDIM + j0 + tr] = ysq;
    }

    // epilogue: store raw dot partials
    const int gr = lane >> 2, gc = lane & 3;
    float* gout = g_part[ks];
#pragma unroll
    for (int mi = 0; mi < 2; ++mi) {
#pragma unroll
        for (int nb = 0; nb < 4; ++nb) {
            const int jc = j0w + nb * 8 + gc * 2;
            const int grow = b * CDIM + i0 + i0w + mi * 16 + gr;
            *(float2*)&gout[(size_t)grow * CDIM + j0 + jc] =
                make_float2(acc[mi][nb][0], acc[mi][nb][1]);
            *(float2*)&gout[(size_t)(grow + 8) * CDIM + j0 + jc] =
                make_float2(acc[mi][nb][2], acc[mi][nb][3]);
        }
    }
}

// ---------------------------------------------------------------------------
// 2) argmin of (yn[j] - 2*dot) with exact-fp32 rescue. One block per row.
// ---------------------------------------------------------------------------
__global__ void __launch_bounds__(256) rescore_kernel(const float* __restrict__ X,
                                                      const float* __restrict__ Y) {
    const int row = blockIdx.x;           // b*CDIM + i
    const int b   = row >> 8;
    const int t   = threadIdx.x;

    __shared__ float s_red[8];
    __shared__ float s_minv;
    __shared__ int   s_cnt;
    __shared__ int   s_lst[256];

    const size_t off = (size_t)row * CDIM + t;
    float dot = 0.f, yn = 0.f;
#pragma unroll
    for (int k = 0; k < KSPLIT; ++k) {
        dot += g_part[k][off];
        yn  += g_ynp[k][b * CDIM + t];
    }
    float d = yn - 2.f * dot;

    float vv = d;
#pragma unroll
    for (int o = 16; o; o >>= 1) vv = fminf(vv, __shfl_down_sync(0xffffffffu, vv, o));
    if ((t & 31) == 0) s_red[t >> 5] = vv;
    __syncthreads();
    if (t == 0) {
        float m = s_red[0];
#pragma unroll
        for (int i = 1; i < 8; ++i) m = fminf(m, s_red[i]);
        s_minv = m;
        s_cnt = 0;
    }
    __syncthreads();

    if (d <= s_minv + TAU) {
        int pos = atomicAdd(&s_cnt, 1);
        s_lst[pos] = t;
    }
    __syncthreads();

    const int n = s_cnt;
    if (n == 1) {
        if (t == 0) g_idx[row] = s_lst[0];
        return;
    }

    const float* xr = X + (size_t)row * HW;
    float bestv = 3.4e38f;
    int   bestj = 0x7fffffff;
    for (int c = 0; c < n; ++c) {
        const int j = s_lst[c];
        const float* yr = Y + (size_t)(b * CDIM + j) * HW;
        float s = 0.f;
#pragma unroll
        for (int q = 0; q < 4; ++q) {
            float4 xv = ((const float4*)xr)[t + q * 256];
            float4 yv = ((const float4*)yr)[t + q * 256];
            float dx = xv.x - yv.x, dy = xv.y - yv.y, dz = xv.z - yv.z, dw = xv.w - yv.w;
            s += dx * dx + dy * dy + dz * dz + dw * dw;
        }
#pragma unroll
        for (int o = 16; o; o >>= 1) s += __shfl_down_sync(0xffffffffu, s, o);
        if ((t & 31) == 0) s_red[t >> 5] = s;
        __syncthreads();
        if (t == 0) {
            float tot = 0.f;
#pragma unroll
            for (int i = 0; i < 8; ++i) tot += s_red[i];
            if (tot < bestv || (tot == bestv && j < bestj)) { bestv = tot; bestj = j; }
        }
        __syncthreads();
    }
    if (t == 0) g_idx[row] = bestj;
}

// ---------------------------------------------------------------------------
// 3) gather: out[b,i,:] = Y[b, g_idx[b,i], :]
// ---------------------------------------------------------------------------
__global__ void __launch_bounds__(256) gather_kernel(const float* __restrict__ Y,
                                                     float* __restrict__ out) {
    int row  = blockIdx.x >> 2;
    int part = blockIdx.x & 3;
    int bb   = row >> 8;
    int src  = g_idx[row];
    const float4* yp = (const float4*)(Y + (size_t)(bb * CDIM + src) * HW);
    float4*       op = (float4*)(out + (size_t)row * HW);
    int e = part * 256 + threadIdx.x;
    op[e] = yp[e];
}

// ---------------------------------------------------------------------------
extern "C" void kernel_launch(void* const* d_in, const int* in_sizes, int n_in,
                              void* d_out, int out_size) {
    const float* x = (const float*)d_in[0];
    const float* y = (const float*)d_in[1];
    float* out = (float*)d_out;

    cudaFuncSetAttribute(gemm_kernel,
                         cudaFuncAttributeMaxDynamicSharedMemorySize, SMEM_BYTES);

    dim3 g(CDIM / 128, CDIM / 128, BATCH * KSPLIT);   // 2 x 2 x 128 = 512 CTAs
    gemm_kernel<<<g, 512, SMEM_BYTES>>>(x, y);

    rescore_kernel<<<BATCH * CDIM, 256>>>(x, y);

    gather_kernel<<<BATCH * CDIM * 4, 256>>>(y, out);
}

// round 13
// speedup vs baseline: 2.1434x; 1.1023x over previous
#include <cuda_runtime.h>
#include <cuda_bf16.h>
#include <stdint.h>

#define BATCH 16
#define CDIM 256
#define HW 4096
#define KC 32                  // k per chunk (fp32 elems) = two k16 MMA steps
#define KSPLIT 8
#define KSEG (HW / KSPLIT)     // 512
#define NKCS (KSEG / KC)       // 16 chunks
#define SSTR 40                // bf16 smem row stride (80B; conflict-free ldsm)
#define TAU 8.0f

// dynamic smem layout (bytes):
// fp32 ring: 2 stages x (A 16KB + B 16KB)   [0, 65536)
// bf16 A double buffer: 2 x 10240           [65536, 86016)
// bf16 B double buffer: 2 x 10240           [86016, 106496)
#define F32A(s) ((s) * 32768)
#define F32B(s) ((s) * 32768 + 16384)
#define BFA(p) (65536 + (p) * 10240)
#define BFB(p) (86016 + (p) * 10240)
#define SMEM_BYTES 106496

__device__ float g_part[KSPLIT][BATCH * CDIM * CDIM];   // dot partials
__device__ float g_ynp[KSPLIT][BATCH * CDIM];           // |y|^2 partials

// ---------------- helpers ----------------
__device__ __forceinline__ uint32_t bf2(float x, float y) {
    __nv_bfloat162 h = __floats2bfloat162_rn(x, y);
    return *reinterpret_cast<uint32_t*>(&h);
}
__device__ __forceinline__ uint32_t smaddr(const void* p) {
    return (uint32_t)__cvta_generic_to_shared(p);
}
__device__ __forceinline__ void cpasync16(uint32_t dst, const float* src) {
    asm volatile("cp.async.cg.shared.global [%0], [%1], 16;" :: "r"(dst), "l"(src));
}
__device__ __forceinline__ void cp_commit() {
    asm volatile("cp.async.commit_group;" ::: "memory");
}
__device__ __forceinline__ void cp_wait1() {
    asm volatile("cp.async.wait_group 1;" ::: "memory");
}
__device__ __forceinline__ void ldsm4(uint32_t a, uint32_t* r) {
    asm volatile("ldmatrix.sync.aligned.m8n8.x4.shared.b16 {%0,%1,%2,%3}, [%4];"
                 : "=r"(r[0]), "=r"(r[1]), "=r"(r[2]), "=r"(r[3]) : "r"(a));
}
__device__ __forceinline__ void mma_bf16(float* d, const uint32_t* a, const uint32_t* b) {
    asm volatile("mma.sync.aligned.m16n8k16.row.col.f32.bf16.bf16.f32 "
                 "{%0,%1,%2,%3}, {%4,%5,%6,%7}, {%8,%9}, {%0,%1,%2,%3};"
                 : "+f"(d[0]), "+f"(d[1]), "+f"(d[2]), "+f"(d[3])
                 : "r"(a[0]), "r"(a[1]), "r"(a[2]), "r"(a[3]), "r"(b[0]), "r"(b[1]));
}

// ---------------------------------------------------------------------------
// 1) dot partials over one k-segment. cp.async fp32 ring (2 stages, k32) ->
//    in-smem cvt to bf16 (double buffer) -> ldsm + m16n8k16 bf16 MMA.
//    CTA 128(i) x 128(j), 512 threads, 16 warps 4(i)x4(j), warp tile 32x32.
// ---------------------------------------------------------------------------
__global__ void __launch_bounds__(512, 2) gemm_kernel(const float* __restrict__ X,
                                                      const float* __restrict__ Y) {
    extern __shared__ __align__(16) uint8_t sm[];
    const uint32_t smu = smaddr(sm);

    const int t  = threadIdx.x;
    const int b  = blockIdx.z >> 3;
    const int ks = blockIdx.z & 7;
    const int i0 = blockIdx.y * 128;
    const int j0 = blockIdx.x * 128;

    // loader: o = 16B segment (0..7) of the 128B k32 row; rows tr and tr+64
    const int o  = t & 7;
    const int tr = t >> 3;    // 0..63
    const float* aSrc = X + (size_t)(b * CDIM + i0 + tr) * HW + ks * KSEG + o * 4;
    const float* bSrc = Y + (size_t)(b * CDIM + j0 + tr) * HW + ks * KSEG + o * 4;
    const uint32_t f0 = (uint32_t)tr * 128u + (uint32_t)o * 16u;   // within fp32 stage
    const uint32_t g0 = 2u * ((uint32_t)tr * SSTR) + (uint32_t)o * 8u;  // bf16 byte off
    const size_t ROW64 = (size_t)64 * HW;

    // consumer fragment mapping (R7/R12-verified)
    const int lane = t & 31;
    const int w    = t >> 5;
    const int i0w  = (w >> 2) * 32;
    const int j0w  = (w & 3) * 32;
    const uint32_t aoff = 2u * ((uint32_t)(i0w + (lane & 15)) * SSTR + (uint32_t)((lane >> 4) * 8));
    const uint32_t boff = 2u * ((uint32_t)(j0w + (lane & 7) + ((lane >> 4) << 3)) * SSTR
                                + (uint32_t)(((lane >> 3) & 1) * 8));

    const bool doYn = (blockIdx.y == 0);
    float ysq0 = 0.f, ysq1 = 0.f;

    float acc[2][4][4];
#pragma unroll
    for (int m = 0; m < 2; ++m)
#pragma unroll
        for (int n = 0; n < 4; ++n)
#pragma unroll
            for (int e = 0; e < 4; ++e) acc[m][n][e] = 0.f;

    // prologue: prefetch chunks 0,1 into stages 0,1
#pragma unroll
    for (int pc = 0; pc < 2; ++pc) {
        cpasync16(smu + F32A(pc) + f0, aSrc + pc * KC);
        cpasync16(smu + F32A(pc) + f0 + 8192u, aSrc + ROW64 + pc * KC);
        cpasync16(smu + F32B(pc) + f0, bSrc + pc * KC);
        cpasync16(smu + F32B(pc) + f0 + 8192u, bSrc + ROW64 + pc * KC);
        cp_commit();
    }

    for (int kc = 0; kc < NKCS; ++kc) {
        const int s = kc & 1;

        cp_wait1();    // chunk kc landed (chunk kc+1 may still be in flight)

        // cvt: read back own 4 x 16B, convert, store to bf16 tile s
        float4 va0 = *(const float4*)((const float*)(sm + F32A(s) + f0));
        float4 va1 = *(const float4*)((const float*)(sm + F32A(s) + f0 + 8192u));
        float4 vb0 = *(const float4*)((const float*)(sm + F32B(s) + f0));
        float4 vb1 = *(const float4*)((const float*)(sm + F32B(s) + f0 + 8192u));
        if (doYn) {
            ysq0 += vb0.x * vb0.x + vb0.y * vb0.y + vb0.z * vb0.z + vb0.w * vb0.w;
            ysq1 += vb1.x * vb1.x + vb1.y * vb1.y + vb1.z * vb1.z + vb1.w * vb1.w;
        }
        *(uint2*)(sm + BFA(s) + g0)         = make_uint2(bf2(va0.x, va0.y), bf2(va0.z, va0.w));
        *(uint2*)(sm + BFA(s) + g0 + 5120u) = make_uint2(bf2(va1.x, va1.y), bf2(va1.z, va1.w));
        *(uint2*)(sm + BFB(s) + g0)         = make_uint2(bf2(vb0.x, vb0.y), bf2(vb0.z, vb0.w));
        *(uint2*)(sm + BFB(s) + g0 + 5120u) = make_uint2(bf2(vb1.x, vb1.y), bf2(vb1.z, vb1.w));

        __syncthreads();   // bf16 tile s complete; fp32 stage s consumed by all

        // refill stage s with chunk kc+2
        if (kc + 2 < NKCS) {
            cpasync16(smu + F32A(s) + f0, aSrc + (kc + 2) * KC);
            cpasync16(smu + F32A(s) + f0 + 8192u, aSrc + ROW64 + (kc + 2) * KC);
            cpasync16(smu + F32B(s) + f0, bSrc + (kc + 2) * KC);
            cpasync16(smu + F32B(s) + f0 + 8192u, bSrc + ROW64 + (kc + 2) * KC);
        }
        cp_commit();   // uniform: one group per iteration

        // consume: two k16 steps (8 ldsm.x4 + 16 MMA)
#pragma unroll
        for (int st = 0; st < 2; ++st) {
            const uint32_t ko = (uint32_t)st * 32u;   // 16 bf16 = 32B
            uint32_t ah0[4], ah1[4], bh0[4], bh1[4];
            ldsm4(smu + BFA(s) + aoff + ko, ah0);
            ldsm4(smu + BFA(s) + aoff + ko + 2u * 16 * SSTR, ah1);
            ldsm4(smu + BFB(s) + boff + ko, bh0);
            ldsm4(smu + BFB(s) + boff + ko + 2u * 16 * SSTR, bh1);
            mma_bf16(acc[0][0], ah0, bh0);
            mma_bf16(acc[0][1], ah0, bh0 + 2);
            mma_bf16(acc[0][2], ah0, bh1);
            mma_bf16(acc[0][3], ah0, bh1 + 2);
            mma_bf16(acc[1][0], ah1, bh0);
            mma_bf16(acc[1][1], ah1, bh0 + 2);
            mma_bf16(acc[1][2], ah1, bh1);
            mma_bf16(acc[1][3], ah1, bh1 + 2);
        }
    }

    if (doYn) {        // |y|^2 partials (exact fp32): 8 lanes per row
        ysq0 += __shfl_xor_sync(0xffffffffu, ysq0, 1);
        ysq0 += __shfl_xor_sync(0xffffffffu, ysq0, 2);
        ysq0 += __shfl_xor_sync(0xffffffffu, ysq0, 4);
        ysq1 += __shfl_xor_sync(0xffffffffu, ysq1, 1);
        ysq1 += __shfl_xor_sync(0xffffffffu, ysq1, 2);
        ysq1 += __shfl_xor_sync(0xffffffffu, ysq1, 4);
        if (o == 0) {
            g_ynp[ks][b * CDIM + j0 + tr]      = ysq0;
            g_ynp[ks][b * CDIM + j0 + tr + 64] = ysq1;
        }
    }

    // epilogue: store raw dot partials
    const int gr = lane >> 2, gc = lane & 3;
    float* gout = g_part[ks];
#pragma unroll
    for (int mi = 0; mi < 2; ++mi) {
#pragma unroll
        for (int nb = 0; nb < 4; ++nb) {
            const int jc = j0w + nb * 8 + gc * 2;
            const int grow = b * CDIM + i0 + i0w + mi * 16 + gr;
            *(float2*)&gout[(size_t)grow * CDIM + j0 + jc] =
                make_float2(acc[mi][nb][0], acc[mi][nb][1]);
            *(float2*)&gout[(size_t)(grow + 8) * CDIM + j0 + jc] =
                make_float2(acc[mi][nb][2], acc[mi][nb][3]);
        }
    }
}

// ---------------------------------------------------------------------------
// 2) fused: argmin of (yn[j] - 2*dot) + exact-fp32 rescue + row gather.
//    One block per output row.
// ---------------------------------------------------------------------------
__global__ void __launch_bounds__(256) rescore_gather_kernel(const float* __restrict__ X,
                                                             const float* __restrict__ Y,
                                                             float* __restrict__ out) {
    const int row = blockIdx.x;           // b*CDIM + i
    const int b   = row >> 8;
    const int t   = threadIdx.x;

    __shared__ float s_red[8];
    __shared__ float s_minv;
    __shared__ int   s_cnt;
    __shared__ int   s_lst[256];
    __shared__ int   s_bestj;

    const size_t off = (size_t)row * CDIM + t;
    float dot = 0.f, yn = 0.f;
#pragma unroll
    for (int k = 0; k < KSPLIT; ++k) {
        dot += g_part[k][off];
        yn  += g_ynp[k][b * CDIM + t];
    }
    float d = yn - 2.f * dot;

    float vv = d;
#pragma unroll
    for (int o = 16; o; o >>= 1) vv = fminf(vv, __shfl_down_sync(0xffffffffu, vv, o));
    if ((t & 31) == 0) s_red[t >> 5] = vv;
    __syncthreads();
    if (t == 0) {
        float m = s_red[0];
#pragma unroll
        for (int i = 1; i < 8; ++i) m = fminf(m, s_red[i]);
        s_minv = m;
        s_cnt = 0;
    }
    __syncthreads();

    if (d <= s_minv + TAU) {
        int pos = atomicAdd(&s_cnt, 1);
        s_lst[pos] = t;
    }
    __syncthreads();

    const int n = s_cnt;
    if (n == 1) {
        if (t == 0) s_bestj = s_lst[0];
    } else {
        // exact fp32 rescore; tie -> lower j
        const float* xr = X + (size_t)row * HW;
        float bestv = 3.4e38f;
        int   bestj = 0x7fffffff;
        for (int c = 0; c < n; ++c) {
            const int j = s_lst[c];
            const float* yr = Y + (size_t)(b * CDIM + j) * HW;
            float s = 0.f;
#pragma unroll
            for (int q = 0; q < 4; ++q) {
                float4 xv = ((const float4*)xr)[t + q * 256];
                float4 yv = ((const float4*)yr)[t + q * 256];
                float dx = xv.x - yv.x, dy = xv.y - yv.y, dz = xv.z - yv.z, dw = xv.w - yv.w;
                s += dx * dx + dy * dy + dz * dz + dw * dw;
            }
#pragma unroll
            for (int o = 16; o; o >>= 1) s += __shfl_down_sync(0xffffffffu, s, o);
            if ((t & 31) == 0) s_red[t >> 5] = s;
            __syncthreads();
            if (t == 0) {
                float tot = 0.f;
#pragma unroll
                for (int i = 0; i < 8; ++i) tot += s_red[i];
                if (tot < bestv || (tot == bestv && j < bestj)) { bestv = tot; bestj = j; }
            }
            __syncthreads();
        }
        if (t == 0) s_bestj = bestj;
    }
    __syncthreads();

    // gather: copy Y[b, bestj, :] -> out[row, :]  (1024 float4, 4 per thread)
    const float4* yp = (const float4*)(Y + (size_t)(b * CDIM + s_bestj) * HW);
    float4*       op = (float4*)(out + (size_t)row * HW);
#pragma unroll
    for (int q = 0; q < 4; ++q)
        op[t + q * 256] = yp[t + q * 256];
}

// ---------------------------------------------------------------------------
extern "C" void kernel_launch(void* const* d_in, const int* in_sizes, int n_in,
                              void* d_out, int out_size) {
    const float* x = (const float*)d_in[0];
    const float* y = (const float*)d_in[1];
    float* out = (float*)d_out;

    cudaFuncSetAttribute(gemm_kernel,
                         cudaFuncAttributeMaxDynamicSharedMemorySize, SMEM_BYTES);

    dim3 g(CDIM / 128, CDIM / 128, BATCH * KSPLIT);   // 2 x 2 x 128 = 512 CTAs
    gemm_kernel<<<g, 512, SMEM_BYTES>>>(x, y);

    rescore_gather_kernel<<<BATCH * CDIM, 256>>>(x, y, out);
}

// round 14
// speedup vs baseline: 2.2194x; 1.0355x over previous
#include <cuda_runtime.h>
#include <cuda_bf16.h>
#include <stdint.h>

#define BATCH 16
#define CDIM 256
#define HW 4096
#define KC 32                  // k per chunk (fp32 elems) = two k16 MMA steps
#define KSPLIT 8
#define KSEG (HW / KSPLIT)     // 512
#define NKCS (KSEG / KC)       // 16 chunks
#define SSTR 40                // bf16 smem row stride (80B; conflict-free ldsm)
#define TAU 8.0f

// dynamic smem layout (bytes):
// fp32 ring: 2 stages x (A 16KB + B 16KB)   [0, 65536)
// bf16 A double buffer: 2 x 10240           [65536, 86016)
// bf16 B double buffer: 2 x 10240           [86016, 106496)
#define F32A(s) ((s) * 32768)
#define F32B(s) ((s) * 32768 + 16384)
#define BFA(p) (65536 + (p) * 10240)
#define BFB(p) (86016 + (p) * 10240)
#define SMEM_BYTES 106496

__device__ __nv_bfloat16 g_part[KSPLIT][BATCH * CDIM * CDIM];   // 16 MB dot partials
__device__ float g_ynp[KSPLIT][BATCH * CDIM];                   // |y|^2 partials (fp32)

// ---------------- helpers ----------------
__device__ __forceinline__ uint32_t bf2(float x, float y) {
    __nv_bfloat162 h = __floats2bfloat162_rn(x, y);
    return *reinterpret_cast<uint32_t*>(&h);
}
__device__ __forceinline__ uint32_t smaddr(const void* p) {
    return (uint32_t)__cvta_generic_to_shared(p);
}
__device__ __forceinline__ void cpasync16(uint32_t dst, const float* src) {
    asm volatile("cp.async.cg.shared.global [%0], [%1], 16;" :: "r"(dst), "l"(src));
}
__device__ __forceinline__ void cp_commit() {
    asm volatile("cp.async.commit_group;" ::: "memory");
}
__device__ __forceinline__ void cp_wait1() {
    asm volatile("cp.async.wait_group 1;" ::: "memory");
}
__device__ __forceinline__ void ldsm4(uint32_t a, uint32_t* r) {
    asm volatile("ldmatrix.sync.aligned.m8n8.x4.shared.b16 {%0,%1,%2,%3}, [%4];"
                 : "=r"(r[0]), "=r"(r[1]), "=r"(r[2]), "=r"(r[3]) : "r"(a));
}
__device__ __forceinline__ void mma_bf16(float* d, const uint32_t* a, const uint32_t* b) {
    asm volatile("mma.sync.aligned.m16n8k16.row.col.f32.bf16.bf16.f32 "
                 "{%0,%1,%2,%3}, {%4,%5,%6,%7}, {%8,%9}, {%0,%1,%2,%3};"
                 : "+f"(d[0]), "+f"(d[1]), "+f"(d[2]), "+f"(d[3])
                 : "r"(a[0]), "r"(a[1]), "r"(a[2]), "r"(a[3]), "r"(b[0]), "r"(b[1]));
}

// ---------------------------------------------------------------------------
// 1) dot partials over one k-segment. cp.async fp32 ring (2 stages, k32) ->
//    in-smem cvt to bf16 (double buffer) -> ldsm + m16n8k16 bf16 MMA.
//    CTA 128(i) x 128(j), 512 threads, 16 warps 4(i)x4(j), warp tile 32x32.
// ---------------------------------------------------------------------------
__global__ void __launch_bounds__(512, 2) gemm_kernel(const float* __restrict__ X,
                                                      const float* __restrict__ Y) {
    extern __shared__ __align__(16) uint8_t sm[];
    const uint32_t smu = smaddr(sm);

    const int t  = threadIdx.x;
    const int b  = blockIdx.z >> 3;
    const int ks = blockIdx.z & 7;
    const int i0 = blockIdx.y * 128;
    const int j0 = blockIdx.x * 128;

    // loader: o = 16B segment (0..7) of the 128B k32 row; rows tr and tr+64
    const int o  = t & 7;
    const int tr = t >> 3;    // 0..63
    const float* aSrc = X + (size_t)(b * CDIM + i0 + tr) * HW + ks * KSEG + o * 4;
    const float* bSrc = Y + (size_t)(b * CDIM + j0 + tr) * HW + ks * KSEG + o * 4;
    const uint32_t f0 = (uint32_t)tr * 128u + (uint32_t)o * 16u;   // within fp32 stage
    const uint32_t g0 = 2u * ((uint32_t)tr * SSTR) + (uint32_t)o * 8u;  // bf16 byte off
    const size_t ROW64 = (size_t)64 * HW;

    // consumer fragment mapping (R7/R12-verified)
    const int lane = t & 31;
    const int w    = t >> 5;
    const int i0w  = (w >> 2) * 32;
    const int j0w  = (w & 3) * 32;
    const uint32_t aoff = 2u * ((uint32_t)(i0w + (lane & 15)) * SSTR + (uint32_t)((lane >> 4) * 8));
    const uint32_t boff = 2u * ((uint32_t)(j0w + (lane & 7) + ((lane >> 4) << 3)) * SSTR
                                + (uint32_t)(((lane >> 3) & 1) * 8));

    const bool doYn = (blockIdx.y == 0);
    float ysq0 = 0.f, ysq1 = 0.f;

    float acc[2][4][4];
#pragma unroll
    for (int m = 0; m < 2; ++m)
#pragma unroll
        for (int n = 0; n < 4; ++n)
#pragma unroll
            for (int e = 0; e < 4; ++e) acc[m][n][e] = 0.f;

    // prologue: prefetch chunks 0,1 into stages 0,1
#pragma unroll
    for (int pc = 0; pc < 2; ++pc) {
        cpasync16(smu + F32A(pc) + f0, aSrc + pc * KC);
        cpasync16(smu + F32A(pc) + f0 + 8192u, aSrc + ROW64 + pc * KC);
        cpasync16(smu + F32B(pc) + f0, bSrc + pc * KC);
        cpasync16(smu + F32B(pc) + f0 + 8192u, bSrc + ROW64 + pc * KC);
        cp_commit();
    }

    for (int kc = 0; kc < NKCS; ++kc) {
        const int s = kc & 1;

        cp_wait1();    // chunk kc landed (chunk kc+1 may still be in flight)

        // cvt: read back own 4 x 16B, convert, store to bf16 tile s
        float4 va0 = *(const float4*)((const float*)(sm + F32A(s) + f0));
        float4 va1 = *(const float4*)((const float*)(sm + F32A(s) + f0 + 8192u));
        float4 vb0 = *(const float4*)((const float*)(sm + F32B(s) + f0));
        float4 vb1 = *(const float4*)((const float*)(sm + F32B(s) + f0 + 8192u));
        if (doYn) {
            ysq0 += vb0.x * vb0.x + vb0.y * vb0.y + vb0.z * vb0.z + vb0.w * vb0.w;
            ysq1 += vb1.x * vb1.x + vb1.y * vb1.y + vb1.z * vb1.z + vb1.w * vb1.w;
        }
        *(uint2*)(sm + BFA(s) + g0)         = make_uint2(bf2(va0.x, va0.y), bf2(va0.z, va0.w));
        *(uint2*)(sm + BFA(s) + g0 + 5120u) = make_uint2(bf2(va1.x, va1.y), bf2(va1.z, va1.w));
        *(uint2*)(sm + BFB(s) + g0)         = make_uint2(bf2(vb0.x, vb0.y), bf2(vb0.z, vb0.w));
        *(uint2*)(sm + BFB(s) + g0 + 5120u) = make_uint2(bf2(vb1.x, vb1.y), bf2(vb1.z, vb1.w));

        __syncthreads();   // bf16 tile s complete; fp32 stage s consumed by all

        // refill stage s with chunk kc+2
        if (kc + 2 < NKCS) {
            cpasync16(smu + F32A(s) + f0, aSrc + (kc + 2) * KC);
            cpasync16(smu + F32A(s) + f0 + 8192u, aSrc + ROW64 + (kc + 2) * KC);
            cpasync16(smu + F32B(s) + f0, bSrc + (kc + 2) * KC);
            cpasync16(smu + F32B(s) + f0 + 8192u, bSrc + ROW64 + (kc + 2) * KC);
        }
        cp_commit();   // uniform: one group per iteration

        // consume: two k16 steps (8 ldsm.x4 + 16 MMA)
#pragma unroll
        for (int st = 0; st < 2; ++st) {
            const uint32_t ko = (uint32_t)st * 32u;   // 16 bf16 = 32B
            uint32_t ah0[4], ah1[4], bh0[4], bh1[4];
            ldsm4(smu + BFA(s) + aoff + ko, ah0);
            ldsm4(smu + BFA(s) + aoff + ko + 2u * 16 * SSTR, ah1);
            ldsm4(smu + BFB(s) + boff + ko, bh0);
            ldsm4(smu + BFB(s) + boff + ko + 2u * 16 * SSTR, bh1);
            mma_bf16(acc[0][0], ah0, bh0);
            mma_bf16(acc[0][1], ah0, bh0 + 2);
            mma_bf16(acc[0][2], ah0, bh1);
            mma_bf16(acc[0][3], ah0, bh1 + 2);
            mma_bf16(acc[1][0], ah1, bh0);
            mma_bf16(acc[1][1], ah1, bh0 + 2);
            mma_bf16(acc[1][2], ah1, bh1);
            mma_bf16(acc[1][3], ah1, bh1 + 2);
        }
    }

    if (doYn) {        // |y|^2 partials (exact fp32): 8 lanes per row
        ysq0 += __shfl_xor_sync(0xffffffffu, ysq0, 1);
        ysq0 += __shfl_xor_sync(0xffffffffu, ysq0, 2);
        ysq0 += __shfl_xor_sync(0xffffffffu, ysq0, 4);
        ysq1 += __shfl_xor_sync(0xffffffffu, ysq1, 1);
        ysq1 += __shfl_xor_sync(0xffffffffu, ysq1, 2);
        ysq1 += __shfl_xor_sync(0xffffffffu, ysq1, 4);
        if (o == 0) {
            g_ynp[ks][b * CDIM + j0 + tr]      = ysq0;
            g_ynp[ks][b * CDIM + j0 + tr + 64] = ysq1;
        }
    }

    // epilogue: store dot partials as packed bf16 pairs (halved traffic)
    const int gr = lane >> 2, gc = lane & 3;
    __nv_bfloat16* gout = g_part[ks];
#pragma unroll
    for (int mi = 0; mi < 2; ++mi) {
#pragma unroll
        for (int nb = 0; nb < 4; ++nb) {
            const int jc = j0w + nb * 8 + gc * 2;
            const int grow = b * CDIM + i0 + i0w + mi * 16 + gr;
            *(uint32_t*)&gout[(size_t)grow * CDIM + j0 + jc] =
                bf2(acc[mi][nb][0], acc[mi][nb][1]);
            *(uint32_t*)&gout[(size_t)(grow + 8) * CDIM + j0 + jc] =
                bf2(acc[mi][nb][2], acc[mi][nb][3]);
        }
    }
}

// ---------------------------------------------------------------------------
// 2) fused: argmin of (yn[j] - 2*dot) + exact-fp32 rescue + row gather.
//    One block per output row.
// ---------------------------------------------------------------------------
__global__ void __launch_bounds__(256) rescore_gather_kernel(const float* __restrict__ X,
                                                             const float* __restrict__ Y,
                                                             float* __restrict__ out) {
    const int row = blockIdx.x;           // b*CDIM + i
    const int b   = row >> 8;
    const int t   = threadIdx.x;

    __shared__ float s_red[8];
    __shared__ float s_minv;
    __shared__ int   s_cnt;
    __shared__ int   s_lst[256];
    __shared__ int   s_bestj;

    const size_t off = (size_t)row * CDIM + t;
    float dot = 0.f, yn = 0.f;
#pragma unroll
    for (int k = 0; k < KSPLIT; ++k) {
        dot += __bfloat162float(g_part[k][off]);
        yn  += g_ynp[k][b * CDIM + t];
    }
    float d = yn - 2.f * dot;

    float vv = d;
#pragma unroll
    for (int o = 16; o; o >>= 1) vv = fminf(vv, __shfl_down_sync(0xffffffffu, vv, o));
    if ((t & 31) == 0) s_red[t >> 5] = vv;
    __syncthreads();
    if (t == 0) {
        float m = s_red[0];
#pragma unroll
        for (int i = 1; i < 8; ++i) m = fminf(m, s_red[i]);
        s_minv = m;
        s_cnt = 0;
    }
    __syncthreads();

    if (d <= s_minv + TAU) {
        int pos = atomicAdd(&s_cnt, 1);
        s_lst[pos] = t;
    }
    __syncthreads();

    const int n = s_cnt;
    if (n == 1) {
        if (t == 0) s_bestj = s_lst[0];
    } else {
        // exact fp32 rescore; tie -> lower j
        const float* xr = X + (size_t)row * HW;
        float bestv = 3.4e38f;
        int   bestj = 0x7fffffff;
        for (int c = 0; c < n; ++c) {
            const int j = s_lst[c];
            const float* yr = Y + (size_t)(b * CDIM + j) * HW;
            float s = 0.f;
#pragma unroll
            for (int q = 0; q < 4; ++q) {
                float4 xv = ((const float4*)xr)[t + q * 256];
                float4 yv = ((const float4*)yr)[t + q * 256];
                float dx = xv.x - yv.x, dy = xv.y - yv.y, dz = xv.z - yv.z, dw = xv.w - yv.w;
                s += dx * dx + dy * dy + dz * dz + dw * dw;
            }
#pragma unroll
            for (int o = 16; o; o >>= 1) s += __shfl_down_sync(0xffffffffu, s, o);
            if ((t & 31) == 0) s_red[t >> 5] = s;
            __syncthreads();
            if (t == 0) {
                float tot = 0.f;
#pragma unroll
                for (int i = 0; i < 8; ++i) tot += s_red[i];
                if (tot < bestv || (tot == bestv && j < bestj)) { bestv = tot; bestj = j; }
            }
            __syncthreads();
        }
        if (t == 0) s_bestj = bestj;
    }
    __syncthreads();

    // gather: copy Y[b, bestj, :] -> out[row, :]  (1024 float4, 4 per thread)
    const float4* yp = (const float4*)(Y + (size_t)(b * CDIM + s_bestj) * HW);
    float4*       op = (float4*)(out + (size_t)row * HW);
#pragma unroll
    for (int q = 0; q < 4; ++q)
        op[t + q * 256] = yp[t + q * 256];
}

// ---------------------------------------------------------------------------
extern "C" void kernel_launch(void* const* d_in, const int* in_sizes, int n_in,
                              void* d_out, int out_size) {
    const float* x = (const float*)d_in[0];
    const float* y = (const float*)d_in[1];
    float* out = (float*)d_out;

    cudaFuncSetAttribute(gemm_kernel,
                         cudaFuncAttributeMaxDynamicSharedMemorySize, SMEM_BYTES);

    dim3 g(CDIM / 128, CDIM / 128, BATCH * KSPLIT);   // 2 x 2 x 128 = 512 CTAs
    gemm_kernel<<<g, 512, SMEM_BYTES>>>(x, y);

    rescore_gather_kernel<<<BATCH * CDIM, 256>>>(x, y, out);
}